// round 2
// baseline (speedup 1.0000x reference)
#include <cuda_runtime.h>
#include <math.h>

// ---------------- problem constants ----------------
#define DIMC      64
#define HW        256          // 16x16
#define BATCH     256
#define EMB_DIM   45184
#define OFF_CNNW  0
#define OFF_CNNB  36864
#define OFF_PROJW 36928
#define OFF_PROJB 45120
#define BHW       (BATCH*DIMC*HW)   // 4194304 floats = 16 MB

// scratch: module outputs h1,h2 and projected conv-input
__device__ float g_h1[BHW];
__device__ float g_h2[BHW];
__device__ float g_ci[BHW];

__device__ __forceinline__ void softmax_n(const float* x, float* y, int n) {
    float m = x[0];
    for (int i = 1; i < n; i++) m = fmaxf(m, x[i]);
    float s = 0.f;
    for (int i = 0; i < n; i++) { y[i] = expf(x[i] - m); s += y[i]; }
    float inv = 1.f / s;
    for (int i = 0; i < n; i++) y[i] *= inv;
}

// =====================================================================
// Kernel P: per-batch projection.
//   ci[b, c, p] = relu-free:  sum_j proj_w[b,c,j] * inp[b,j,p] + proj_b[b,c]
//   inp = concat(lhs, rhs); lhs/rhs = softmax(tau)-weighted stack combos.
// grid 256 (1 CTA / batch), 256 threads, 2 CTAs/SM.
// K split into two halves (lhs then rhs) so the smem stage is only 64 ch.
// =====================================================================
#define P_SMEM_FLOATS (16384 + 64*68 + 64 + 16)

__global__ void __launch_bounds__(256, 2)
proj_kernel(const int* __restrict__ question,
            const float* __restrict__ img,
            const float* __restrict__ emb,
            const float* __restrict__ alpha,
            const float* __restrict__ tau0,
            const float* __restrict__ tau1,
            int mod)
{
    extern __shared__ float sm[];
    float* s_stage = sm;                   // 64*256 = 16384
    float* s_wT    = sm + 16384;           // 64*68  = 4352 (k-major, padded)
    float* s_pb    = sm + 16384 + 4352;    // 64
    float* s_scal  = s_pb + 64;            // [0..2]=a, [3..5]=lhs coefs, [6..8]=rhs coefs

    const int b   = blockIdx.x;
    const int tid = threadIdx.x;

    if (tid == 0) {
        float tmp[4], sf[4];
        for (int t = 0; t < 3; t++) tmp[t] = alpha[mod*3 + t];
        softmax_n(tmp, sf, 3);
        s_scal[0] = sf[0]; s_scal[1] = sf[1]; s_scal[2] = sf[2];
        const int n = mod + 2;
        for (int m = 0; m < n; m++) tmp[m] = tau0[mod*4 + m];
        softmax_n(tmp, sf, n);
        s_scal[3] = sf[1];
        s_scal[4] = (n > 2) ? sf[2] : 0.f;
        s_scal[5] = (n > 3) ? sf[3] : 0.f;
        for (int m = 0; m < n; m++) tmp[m] = tau1[mod*4 + m];
        softmax_n(tmp, sf, n);
        s_scal[6] = sf[1];
        s_scal[7] = (n > 2) ? sf[2] : 0.f;
        s_scal[8] = (n > 3) ? sf[3] : 0.f;
    }
    __syncthreads();

    const float a0 = s_scal[0], a1 = s_scal[1], a2 = s_scal[2];
    const float* r0 = emb + (size_t)question[b*3 + 0] * EMB_DIM;
    const float* r1 = emb + (size_t)question[b*3 + 1] * EMB_DIM;
    const float* r2 = emb + (size_t)question[b*3 + 2] * EMB_DIM;

    if (tid < 64)
        s_pb[tid] = a0*r0[OFF_PROJB + tid] + a1*r1[OFF_PROJB + tid] + a2*r2[OFF_PROJB + tid];

    const int px = tid & 31;
    const int c0 = (tid >> 5) * 8;
    float acc[8][8];

    const float4* img4 = (const float4*)(img  + (size_t)b * DIMC * HW);
    const float4* h14  = (const float4*)(g_h1 + (size_t)b * DIMC * HW);
    const float4* h24  = (const float4*)(g_h2 + (size_t)b * DIMC * HW);
    float4* stage4 = (float4*)s_stage;

    for (int half = 0; half < 2; ++half) {
        const float w1 = s_scal[3 + 3*half + 0];
        const float w2 = s_scal[3 + 3*half + 1];
        const float w3 = s_scal[3 + 3*half + 2];

        // stage = w1*img + w2*h1 + w3*h2   (64 ch x 256 pos)
        for (int e4 = tid; e4 < 4096; e4 += 256) {
            float4 v = img4[e4];
            float4 o;
            o.x = w1*v.x; o.y = w1*v.y; o.z = w1*v.z; o.w = w1*v.w;
            if (mod >= 1) { float4 u = h14[e4]; o.x += w2*u.x; o.y += w2*u.y; o.z += w2*u.z; o.w += w2*u.w; }
            if (mod >= 2) { float4 u = h24[e4]; o.x += w3*u.x; o.y += w3*u.y; o.z += w3*u.z; o.w += w3*u.w; }
            stage4[e4] = o;
        }
        // proj weight (this K-half), stored transposed k-major: s_wT[k*68 + c]
        for (int e = tid; e < 4096; e += 256) {
            const int c  = e >> 6;
            const int kk = e & 63;
            const int off = OFF_PROJW + c*128 + half*64 + kk;
            s_wT[kk*68 + c] = a0*r0[off] + a1*r1[off] + a2*r2[off];
        }
        __syncthreads();

        if (half == 0) {
            #pragma unroll
            for (int ii = 0; ii < 8; ii++) {
                const float pb = s_pb[c0 + ii];
                #pragma unroll
                for (int j = 0; j < 8; j++) acc[ii][j] = pb;
            }
        }
        #pragma unroll 4
        for (int k = 0; k < 64; k++) {
            float av[8], bv[8];
            #pragma unroll
            for (int ii = 0; ii < 8; ii++) av[ii] = s_wT[k*68 + c0 + ii];   // warp-uniform
            #pragma unroll
            for (int j = 0; j < 8; j++)  bv[j]  = s_stage[k*256 + px + 32*j]; // lane-consecutive
            #pragma unroll
            for (int ii = 0; ii < 8; ii++)
                #pragma unroll
                for (int j = 0; j < 8; j++)
                    acc[ii][j] += av[ii]*bv[j];
        }
        __syncthreads();
    }

    float* ci = g_ci + (size_t)b * DIMC * HW;
    #pragma unroll
    for (int ii = 0; ii < 8; ii++)
        #pragma unroll
        for (int j = 0; j < 8; j++)
            ci[(c0 + ii)*256 + px + 32*j] = acc[ii][j];
}

// =====================================================================
// Kernel C: per-batch 3x3 conv with per-batch weights + bias + relu.
//   out[b,o,h,w] = relu( sum_{c,ky,kx} W[b,o,c,ky,kx]*ci_pad[b,c,h+ky,w+kx] + B[b,o] )
// grid 1024 = 256 batches x 4 o-groups(16), 128 threads, 3 CTAs/SM.
// ci staged into zero-haloed (18x18) smem in 16-channel chunks.
// =====================================================================
#define C_SMEM_FLOATS (5184 + 9216 + 16 + 4)

__global__ void __launch_bounds__(128, 3)
conv_kernel(const int* __restrict__ question,
            const float* __restrict__ emb,
            const float* __restrict__ alpha,
            float* __restrict__ out_final,
            int mod)
{
    extern __shared__ float sm[];
    float* s_pad = sm;                 // 16 * 18*18 = 5184
    float* s_wc  = sm + 5184;          // 16 * 576   = 9216
    float* s_cb  = sm + 5184 + 9216;   // 16
    float* s_a   = s_cb + 16;          // 3

    const int b   = blockIdx.x >> 2;
    const int og  = blockIdx.x & 3;
    const int tid = threadIdx.x;

    if (tid == 0) {
        float tmp[3], sf[3];
        for (int t = 0; t < 3; t++) tmp[t] = alpha[mod*3 + t];
        softmax_n(tmp, sf, 3);
        s_a[0] = sf[0]; s_a[1] = sf[1]; s_a[2] = sf[2];
    }
    __syncthreads();

    const float a0 = s_a[0], a1 = s_a[1], a2 = s_a[2];
    const float* r0 = emb + (size_t)question[b*3 + 0] * EMB_DIM;
    const float* r1 = emb + (size_t)question[b*3 + 1] * EMB_DIM;
    const float* r2 = emb + (size_t)question[b*3 + 2] * EMB_DIM;

    if (tid < 16) {
        const int o = og*16 + tid;
        s_cb[tid] = a0*r0[OFF_CNNB + o] + a1*r1[OFF_CNNB + o] + a2*r2[OFF_CNNB + o];
    }
    // zero padded stage once; halo stays zero across channel chunks
    for (int e = tid; e < 5184; e += 128) s_pad[e] = 0.f;

    // build this CTA's 16x576 conv weight slice (fully coalesced float4 reads)
    {
        const float4* w0 = (const float4*)(r0 + og*9216);
        const float4* w1 = (const float4*)(r1 + og*9216);
        const float4* w2 = (const float4*)(r2 + og*9216);
        float4* swc4 = (float4*)s_wc;
        for (int e4 = tid; e4 < 2304; e4 += 128) {
            float4 x = w0[e4], y = w1[e4], z = w2[e4];
            float4 o4;
            o4.x = a0*x.x + a1*y.x + a2*z.x;
            o4.y = a0*x.y + a1*y.y + a2*z.y;
            o4.z = a0*x.z + a1*y.z + a2*z.z;
            o4.w = a0*x.w + a1*y.w + a2*z.w;
            swc4[e4] = o4;
        }
    }
    __syncthreads();

    const int px = tid & 31;
    const int oy = tid >> 5;          // 0..3 -> 4 output channels each
    const int h0 = px >> 4;           // 0/1
    const int wi = px & 15;
    float acc[4][8];
    #pragma unroll
    for (int ii = 0; ii < 4; ii++)
        #pragma unroll
        for (int j = 0; j < 8; j++) acc[ii][j] = 0.f;

    const float4* ci4 = (const float4*)(g_ci + (size_t)b * DIMC * HW);

    for (int cc = 0; cc < 4; ++cc) {
        // stage 16 channels of ci into padded smem (centers only)
        for (int e4 = tid; e4 < 1024; e4 += 128) {
            float4 v = ci4[cc*1024 + e4];
            const int e  = e4 * 4;
            const int cl = e >> 8;
            const int h  = (e >> 4) & 15;
            const int w  = e & 15;
            float* dst = s_pad + cl*324 + (h + 1)*18 + (w + 1);
            dst[0] = v.x; dst[1] = v.y; dst[2] = v.z; dst[3] = v.w;
        }
        __syncthreads();

        #pragma unroll 1
        for (int cl = 0; cl < 16; ++cl) {
            const float* pch  = s_pad + cl*324 + h0*18 + wi;
            const float* wrow = s_wc + (cc*16 + cl)*9;
            #pragma unroll
            for (int ky = 0; ky < 3; ++ky)
                #pragma unroll
                for (int kx = 0; kx < 3; ++kx) {
                    float wv[4];
                    #pragma unroll
                    for (int ii = 0; ii < 4; ii++)
                        wv[ii] = wrow[(oy*4 + ii)*576 + ky*3 + kx];   // warp-uniform
                    #pragma unroll
                    for (int j = 0; j < 8; j++) {
                        const float bv = pch[(2*j + ky)*18 + kx];     // lane-consecutive
                        #pragma unroll
                        for (int ii = 0; ii < 4; ii++)
                            acc[ii][j] += wv[ii]*bv;
                    }
                }
        }
        __syncthreads();
    }

    float* dst = (mod == 0) ? g_h1 : (mod == 1) ? g_h2 : out_final;
    dst += (size_t)b * DIMC * HW;
    #pragma unroll
    for (int ii = 0; ii < 4; ii++) {
        const int o = og*16 + oy*4 + ii;
        const float bb = s_cb[oy*4 + ii];
        #pragma unroll
        for (int j = 0; j < 8; j++)
            dst[o*256 + px + 32*j] = fmaxf(acc[ii][j] + bb, 0.f);
    }
}

// =====================================================================
extern "C" void kernel_launch(void* const* d_in, const int* in_sizes, int n_in,
                              void* d_out, int out_size)
{
    const int*   question = (const int*)  d_in[0];
    const float* img      = (const float*)d_in[1];
    const float* emb      = (const float*)d_in[2];
    const float* alpha    = (const float*)d_in[3];
    const float* tau0     = (const float*)d_in[4];
    const float* tau1     = (const float*)d_in[5];
    float* out = (float*)d_out;

    const int p_smem = P_SMEM_FLOATS * 4;   // 83264 B
    const int c_smem = C_SMEM_FLOATS * 4;   // 57680 B
    cudaFuncSetAttribute(proj_kernel, cudaFuncAttributeMaxDynamicSharedMemorySize, p_smem);
    cudaFuncSetAttribute(conv_kernel, cudaFuncAttributeMaxDynamicSharedMemorySize, c_smem);

    for (int mod = 0; mod < 3; ++mod) {
        proj_kernel<<<BATCH, 256, p_smem>>>(question, img, emb, alpha, tau0, tau1, mod);
        conv_kernel<<<BATCH*4, 128, c_smem>>>(question, emb, alpha, out, mod);
    }
    (void)in_sizes; (void)n_in; (void)out_size;
}